// round 2
// baseline (speedup 1.0000x reference)
#include <cuda_runtime.h>
#include <math.h>
#include <stdint.h>

#define N_NODE   50000
#define N_EDGE   500000
#define N_QUERY  64
#define IN_DIM   128
#define OUT_DIM  128
#define ATTN_DIM 64
#define N_RELTOT 401      // 2*200+1
#define N_TAU    731      // delta_tau in [-365, 365]

// ---- scratch (device globals; no allocation allowed) ----
__device__ float g_nodeWs[N_NODE * ATTN_DIM];    // hidden @ Ws
__device__ float g_relWr [N_RELTOT * ATTN_DIM];  // rela_embed @ Wr
__device__ float g_qpre  [N_QUERY * ATTN_DIM];   // rela_embed[q_rel] @ Wqr_W + b
__device__ float g_tauTab[N_TAU * IN_DIM];       // h_tau(dt)
__device__ float g_tauWT [N_TAU * ATTN_DIM];     // h_tau(dt) @ Wtau
__device__ float g_msg   [N_NODE * IN_DIM];      // segment-summed messages

// ------------------------------------------------------------------
// zero the message accumulator
// ------------------------------------------------------------------
__global__ void zero_msg_kernel() {
    const int n = N_NODE * IN_DIM / 4;
    float4 z = make_float4(0.f, 0.f, 0.f, 0.f);
    float4* p = reinterpret_cast<float4*>(g_msg);
    for (int i = blockIdx.x * blockDim.x + threadIdx.x; i < n;
         i += gridDim.x * blockDim.x)
        p[i] = z;
}

// ------------------------------------------------------------------
// out[M,64] = A[M,128] @ W[128,64]     (which: 0 -> g_nodeWs, 1 -> g_relWr)
// block = 256 threads, 16 rows/block
// ------------------------------------------------------------------
__global__ void matvec64_kernel(const float* __restrict__ A,
                                const float* __restrict__ W,
                                int M, int which) {
    __shared__ float Wsh[IN_DIM * ATTN_DIM];   // 32 KB
    __shared__ float Ash[16][IN_DIM];          // 8 KB
    float* out = which ? g_relWr : g_nodeWs;

    const int tid = threadIdx.x;
    for (int i = tid; i < IN_DIM * ATTN_DIM; i += 256) Wsh[i] = W[i];

    const int r0 = blockIdx.x * 16;
    for (int i = tid; i < 16 * IN_DIM; i += 256) {
        int r = i >> 7, c = i & 127;
        Ash[r][c] = (r0 + r < M) ? A[(size_t)(r0 + r) * IN_DIM + c] : 0.f;
    }
    __syncthreads();

    const int c  = tid & 63;
    const int rg = tid >> 6;          // 4 groups of 4 rows
    float a0 = 0.f, a1 = 0.f, a2 = 0.f, a3 = 0.f;
#pragma unroll 8
    for (int k = 0; k < IN_DIM; k++) {
        float w = Wsh[k * ATTN_DIM + c];
        a0 = fmaf(Ash[rg * 4 + 0][k], w, a0);
        a1 = fmaf(Ash[rg * 4 + 1][k], w, a1);
        a2 = fmaf(Ash[rg * 4 + 2][k], w, a2);
        a3 = fmaf(Ash[rg * 4 + 3][k], w, a3);
    }
    int r = r0 + rg * 4;
    if (r + 0 < M) out[(size_t)(r + 0) * ATTN_DIM + c] = a0;
    if (r + 1 < M) out[(size_t)(r + 1) * ATTN_DIM + c] = a1;
    if (r + 2 < M) out[(size_t)(r + 2) * ATTN_DIM + c] = a2;
    if (r + 3 < M) out[(size_t)(r + 3) * ATTN_DIM + c] = a3;
}

// ------------------------------------------------------------------
// g_qpre[q, c] = rela_embed[q_rel[q]] @ Wqr_W + Wqr_b      <<<64, 64>>>
// ------------------------------------------------------------------
__global__ void qpre_kernel(const int* __restrict__ q_rel,
                            const float* __restrict__ rela,
                            const float* __restrict__ WqrW,
                            const float* __restrict__ Wqrb) {
    const int q = blockIdx.x, c = threadIdx.x;
    const int rel = q_rel[q];
    const float* h = rela + (size_t)rel * IN_DIM;
    float acc = Wqrb[c];
#pragma unroll 8
    for (int k = 0; k < IN_DIM; k++)
        acc = fmaf(h[k], WqrW[k * ATTN_DIM + c], acc);
    g_qpre[q * ATTN_DIM + c] = acc;
}

// ------------------------------------------------------------------
// tau tables: for each integer dt in [-365,365]
//   h_tau[d]  = wt1[d]*dt + bt1[d] + sin(wt2[d]*dt + bt2[d])
//   g_tauWT   = h_tau @ Wtau
// <<<731, 128>>>
// ------------------------------------------------------------------
__global__ void tau_kernel(const float* __restrict__ wt1,
                           const float* __restrict__ bt1,
                           const float* __restrict__ wt2,
                           const float* __restrict__ bt2,
                           const float* __restrict__ Wtau) {
    __shared__ float ht[IN_DIM];
    const int t = blockIdx.x;
    const float dt = (float)(t - 365);
    const int d = threadIdx.x;
    float v = wt1[d] * dt + bt1[d] + sinf(fmaf(wt2[d], dt, bt2[d]));
    ht[d] = v;
    g_tauTab[t * IN_DIM + d] = v;
    __syncthreads();
    if (d < ATTN_DIM) {
        float acc = 0.f;
#pragma unroll 8
        for (int k = 0; k < IN_DIM; k++)
            acc = fmaf(ht[k], Wtau[k * ATTN_DIM + d], acc);
        g_tauWT[t * ATTN_DIM + d] = acc;
    }
}

// ------------------------------------------------------------------
// edge kernel: one warp per edge
// ------------------------------------------------------------------
__global__ void __launch_bounds__(256)
edge_kernel(const int* __restrict__ edges,
            const int* __restrict__ q_tau,
            const float* __restrict__ hidden,
            const float* __restrict__ rela,
            const float* __restrict__ waW,
            const float* __restrict__ wab) {
    const int e    = (blockIdx.x * blockDim.x + threadIdx.x) >> 5;
    const int lane = threadIdx.x & 31;
    if (e >= N_EDGE) return;

    const int* er = edges + (size_t)e * 7;
    const int r_idx = __ldg(er + 0);
    const int rel   = __ldg(er + 2);
    const int tau   = __ldg(er + 4);
    const int sub   = __ldg(er + 5);
    const int obj   = __ldg(er + 6);

    const int tq = __ldg(q_tau + r_idx);
    const int t  = (tau >= 0 ? tau - tq : 0) + 365;   // 0..730

    // attention pre-activation: 4 table lookups, 64 wide (2 per lane)
    const float* nws = g_nodeWs + sub   * ATTN_DIM;
    const float* rwr = g_relWr  + rel   * ATTN_DIM;
    const float* qp  = g_qpre   + r_idx * ATTN_DIM;
    const float* twt = g_tauWT  + t     * ATTN_DIM;

    float p0 = nws[lane]      + rwr[lane]      + qp[lane]      + twt[lane];
    float p1 = nws[lane + 32] + rwr[lane + 32] + qp[lane + 32] + twt[lane + 32];
    p0 = fmaxf(p0, 0.f);
    p1 = fmaxf(p1, 0.f);

    float s = fmaf(p0, __ldg(waW + lane), p1 * __ldg(waW + lane + 32));
#pragma unroll
    for (int off = 16; off > 0; off >>= 1)
        s += __shfl_xor_sync(0xFFFFFFFFu, s, off);
    const float alpha = 1.f / (1.f + expf(-(s + __ldg(wab))));

    // message = alpha * (hs + hr + h_tau), 128 wide -> 4 floats/lane
    const float4 hs = reinterpret_cast<const float4*>(hidden)[(size_t)sub * 32 + lane];
    const float4 hr = reinterpret_cast<const float4*>(rela)[(size_t)rel * 32 + lane];
    const float4 ht = reinterpret_cast<const float4*>(g_tauTab)[(size_t)t * 32 + lane];

    float4 m;
    m.x = alpha * (hs.x + hr.x + ht.x);
    m.y = alpha * (hs.y + hr.y + ht.y);
    m.z = alpha * (hs.z + hr.z + ht.z);
    m.w = alpha * (hs.w + hr.w + ht.w);

    float* dst = g_msg + (size_t)obj * IN_DIM + lane * 4;
    asm volatile("red.global.add.v4.f32 [%0], {%1,%2,%3,%4};"
                 :: "l"(dst), "f"(m.x), "f"(m.y), "f"(m.z), "f"(m.w)
                 : "memory");
}

// ------------------------------------------------------------------
// out[50000,128] = g_msg @ Wh[128,128]
// block = 128 threads (one output column each), 32 rows per block
// ------------------------------------------------------------------
__global__ void __launch_bounds__(128)
out_gemm_kernel(const float* __restrict__ Wh, float* __restrict__ out) {
    __shared__ float At[IN_DIM][36];   // [k][row], padded (stride 144B, 16B-aligned)
    const int c  = threadIdx.x;        // 0..127 = k index on load, col on compute
    const int r0 = blockIdx.x * 32;

#pragma unroll
    for (int i = 0; i < 32; i++) {
        int r = r0 + i;
        At[c][i] = (r < N_NODE) ? g_msg[(size_t)r * IN_DIM + c] : 0.f;
    }
    __syncthreads();

    float acc[32];
#pragma unroll
    for (int i = 0; i < 32; i++) acc[i] = 0.f;

    for (int k = 0; k < IN_DIM; k++) {
        const float w = __ldg(Wh + k * OUT_DIM + c);
#pragma unroll
        for (int j = 0; j < 32; j += 4) {
            float4 a = *reinterpret_cast<const float4*>(&At[k][j]);
            acc[j + 0] = fmaf(a.x, w, acc[j + 0]);
            acc[j + 1] = fmaf(a.y, w, acc[j + 1]);
            acc[j + 2] = fmaf(a.z, w, acc[j + 2]);
            acc[j + 3] = fmaf(a.w, w, acc[j + 3]);
        }
    }
#pragma unroll
    for (int i = 0; i < 32; i++) {
        int r = r0 + i;
        if (r < N_NODE) out[(size_t)r * OUT_DIM + c] = acc[i];
    }
}

// ------------------------------------------------------------------
// host launcher
// ------------------------------------------------------------------
extern "C" void kernel_launch(void* const* d_in, const int* in_sizes, int n_in,
                              void* d_out, int out_size) {
    // input order (dict order): q_sub, q_rel, q_tau, hidden, edges, [n_node],
    // old_nodes_new_idx, rela_embed, Ws, Wr, Wqr_W, Wqr_b, Wtau,
    // w_alpha_W, w_alpha_b, Wh, wt1, bt1, wt2, bt2
    int base = 5;
    if (n_in > 5 && in_sizes[5] == 1) base = 6;   // skip n_node scalar if present

    const int*   q_rel  = (const int*)  d_in[1];
    const int*   q_tau  = (const int*)  d_in[2];
    const float* hidden = (const float*)d_in[3];
    const int*   edges  = (const int*)  d_in[4];
    const float* rela   = (const float*)d_in[base + 1];
    const float* Ws     = (const float*)d_in[base + 2];
    const float* Wr     = (const float*)d_in[base + 3];
    const float* WqrW   = (const float*)d_in[base + 4];
    const float* Wqrb   = (const float*)d_in[base + 5];
    const float* Wtau   = (const float*)d_in[base + 6];
    const float* waW    = (const float*)d_in[base + 7];
    const float* wab    = (const float*)d_in[base + 8];
    const float* Wh     = (const float*)d_in[base + 9];
    const float* wt1    = (const float*)d_in[base + 10];
    const float* bt1    = (const float*)d_in[base + 11];
    const float* wt2    = (const float*)d_in[base + 12];
    const float* bt2    = (const float*)d_in[base + 13];
    float* out = (float*)d_out;

    zero_msg_kernel<<<1600, 256>>>();
    matvec64_kernel<<<(N_NODE + 15) / 16, 256>>>(hidden, Ws, N_NODE, 0);
    matvec64_kernel<<<(N_RELTOT + 15) / 16, 256>>>(rela, Wr, N_RELTOT, 1);
    qpre_kernel<<<N_QUERY, ATTN_DIM>>>(q_rel, rela, WqrW, Wqrb);
    tau_kernel<<<N_TAU, IN_DIM>>>(wt1, bt1, wt2, bt2, Wtau);

    const int warps_per_block = 8;
    const int blocks = (N_EDGE + warps_per_block - 1) / warps_per_block;
    edge_kernel<<<blocks, warps_per_block * 32>>>(edges, q_tau, hidden, rela,
                                                  waW, wab);

    out_gemm_kernel<<<(N_NODE + 31) / 32, 128>>>(Wh, out);
}

// round 3
// speedup vs baseline: 1.0578x; 1.0578x over previous
#include <cuda_runtime.h>
#include <math.h>
#include <stdint.h>

#define N_NODE   50000
#define N_EDGE   500000
#define N_QUERY  64
#define IN_DIM   128
#define OUT_DIM  128
#define ATTN_DIM 64
#define N_RELTOT 401      // 2*200+1
#define N_TAU    731      // delta_tau in [-365, 365]
#define REC      192      // 64 attn cols + 128 projected-message cols

typedef unsigned long long ull;

// ---- scratch (device globals; no allocation allowed) ----
// record layout per index: [0:64) attn projection, [64:192) @Wh projection
__device__ float g_node[N_NODE   * REC];   // [hidden@Ws | hidden@Wh]
__device__ float g_rel [N_RELTOT * REC];   // [rela@Wr   | rela@Wh]
__device__ float g_tau [N_TAU    * REC];   // [h_tau@Wtau| h_tau@Wh]
__device__ float g_qpre[N_QUERY  * ATTN_DIM]; // rela[q_rel]@Wqr_W + b

// ---- packed f32x2 helpers (sm_100+ PTX) ----
__device__ __forceinline__ ull pack2(float lo, float hi) {
    ull r;
    asm("mov.b64 %0, {%1, %2};" : "=l"(r) : "f"(lo), "f"(hi));
    return r;
}
__device__ __forceinline__ void unpack2(ull v, float& lo, float& hi) {
    asm("mov.b64 {%0, %1}, %2;" : "=f"(lo), "=f"(hi) : "l"(v));
}
__device__ __forceinline__ void ffma2(ull& acc, ull a, ull b) {
    asm("fma.rn.f32x2 %0, %1, %2, %0;" : "+l"(acc) : "l"(a), "l"(b));
}

// ------------------------------------------------------------------
// fused prep kernel: blockIdx ranges select the part
//   A [0, NB_A)            : node records   (64 rows/block)
//   B [NB_A, +NB_B)        : rel records    (16 rels/block)
//   C [.., +NB_C)          : qpre           (16 queries/block)
//   D [.., +NB_D)          : tau records    (1 t/block)
// ------------------------------------------------------------------
#define NB_A 782
#define NB_B 26
#define NB_C 4
#define NB_D 731
#define PADR 66   // Ash row stride (even -> 8B-aligned pairs, 2-way write conflict only)

__global__ void __launch_bounds__(256)
prep_kernel(const float* __restrict__ hidden,
            const float* __restrict__ rela,
            const int*   __restrict__ q_rel,
            const float* __restrict__ Ws,
            const float* __restrict__ Wr,
            const float* __restrict__ WqrW,
            const float* __restrict__ Wqrb,
            const float* __restrict__ Wtau,
            const float* __restrict__ Wh,
            const float* __restrict__ wt1,
            const float* __restrict__ bt1,
            const float* __restrict__ wt2,
            const float* __restrict__ bt2) {
    __shared__ float sh[IN_DIM * PADR];   // 33.8 KB, aliased by all parts
    const int tid = threadIdx.x;
    const int blk = blockIdx.x;

    if (blk < NB_A) {
        // ---------- Part A: g_node = [hidden@Ws | hidden@Wh], 64 rows ----------
        const int r0 = blk * 64;
        // Ash[k][row], transposed so row-pairs are contiguous for f32x2
        for (int i = tid; i < 64 * IN_DIM; i += 256) {
            int row = i >> 7, k = i & 127;
            int r = r0 + row;
            sh[k * PADR + row] = (r < N_NODE) ? hidden[(size_t)r * IN_DIM + k] : 0.f;
        }
        __syncthreads();

        // phase 1: Ws -> cols 0..63.  thread: col c, rowgroup rg (16 rows = 8 pairs)
        {
            const int c = tid & 63, rg = tid >> 6;
            ull acc[8];
            const ull z = pack2(0.f, 0.f);
#pragma unroll
            for (int p = 0; p < 8; p++) acc[p] = z;
            const float* base = sh + rg * 16;
#pragma unroll 4
            for (int k = 0; k < IN_DIM; k++) {
                const float w = __ldg(Ws + k * ATTN_DIM + c);
                const ull w2 = pack2(w, w);
                const float* bk = base + k * PADR;
#pragma unroll
                for (int p = 0; p < 8; p++) {
                    ull a2 = *reinterpret_cast<const ull*>(bk + 2 * p);
                    ffma2(acc[p], a2, w2);
                }
            }
#pragma unroll
            for (int p = 0; p < 8; p++) {
                float lo, hi; unpack2(acc[p], lo, hi);
                int r = r0 + rg * 16 + 2 * p;
                if (r     < N_NODE) g_node[(size_t)r       * REC + c] = lo;
                if (r + 1 < N_NODE) g_node[(size_t)(r + 1) * REC + c] = hi;
            }
        }
        // phase 2: Wh -> cols 64..191. thread: col c, rowgroup rg (32 rows = 16 pairs)
        {
            const int c = tid & 127, rg = tid >> 7;
            ull acc[16];
            const ull z = pack2(0.f, 0.f);
#pragma unroll
            for (int p = 0; p < 16; p++) acc[p] = z;
            const float* base = sh + rg * 32;
#pragma unroll 2
            for (int k = 0; k < IN_DIM; k++) {
                const float w = __ldg(Wh + k * OUT_DIM + c);
                const ull w2 = pack2(w, w);
                const float* bk = base + k * PADR;
#pragma unroll
                for (int p = 0; p < 16; p++) {
                    ull a2 = *reinterpret_cast<const ull*>(bk + 2 * p);
                    ffma2(acc[p], a2, w2);
                }
            }
#pragma unroll
            for (int p = 0; p < 16; p++) {
                float lo, hi; unpack2(acc[p], lo, hi);
                int r = r0 + rg * 32 + 2 * p;
                if (r     < N_NODE) g_node[(size_t)r       * REC + 64 + c] = lo;
                if (r + 1 < N_NODE) g_node[(size_t)(r + 1) * REC + 64 + c] = hi;
            }
        }
    } else if (blk < NB_A + NB_B) {
        // ---------- Part B: g_rel = [rela@Wr | rela@Wh], 16 rels ----------
        const int rb = (blk - NB_A) * 16;
        for (int i = tid; i < 16 * IN_DIM; i += 256) {
            int rr = i >> 7, k = i & 127;
            int r = rb + rr;
            sh[rr * IN_DIM + k] = (r < N_RELTOT) ? rela[(size_t)r * IN_DIM + k] : 0.f;
        }
        __syncthreads();
        for (int o = tid; o < 16 * REC; o += 256) {
            int rr = o / REC, c = o - rr * REC;
            int r = rb + rr;
            if (r >= N_RELTOT) continue;
            const float* hrow = sh + rr * IN_DIM;
            float acc = 0.f;
            if (c < 64) {
#pragma unroll 8
                for (int k = 0; k < IN_DIM; k++)
                    acc = fmaf(hrow[k], __ldg(Wr + k * ATTN_DIM + c), acc);
            } else {
                const int cc = c - 64;
#pragma unroll 8
                for (int k = 0; k < IN_DIM; k++)
                    acc = fmaf(hrow[k], __ldg(Wh + k * OUT_DIM + cc), acc);
            }
            g_rel[r * REC + c] = acc;
        }
    } else if (blk < NB_A + NB_B + NB_C) {
        // ---------- Part C: g_qpre, 16 queries ----------
        const int qb = (blk - NB_A - NB_B) * 16;
        for (int i = tid; i < 16 * IN_DIM; i += 256) {
            int qq = i >> 7, k = i & 127;
            int q = qb + qq;
            int rl = (q < N_QUERY) ? __ldg(q_rel + q) : 0;
            sh[qq * IN_DIM + k] = rela[(size_t)rl * IN_DIM + k];
        }
        __syncthreads();
        for (int o = tid; o < 16 * ATTN_DIM; o += 256) {
            int qq = o >> 6, c = o & 63;
            int q = qb + qq;
            if (q >= N_QUERY) continue;
            const float* hrow = sh + qq * IN_DIM;
            float acc = __ldg(Wqrb + c);
#pragma unroll 8
            for (int k = 0; k < IN_DIM; k++)
                acc = fmaf(hrow[k], __ldg(WqrW + k * ATTN_DIM + c), acc);
            g_qpre[q * ATTN_DIM + c] = acc;
        }
    } else {
        // ---------- Part D: g_tau = [h_tau@Wtau | h_tau@Wh], one t ----------
        const int t = blk - NB_A - NB_B - NB_C;
        const float dt = (float)(t - 365);
        if (tid < IN_DIM) {
            float v = wt1[tid] * dt + bt1[tid] + sinf(fmaf(wt2[tid], dt, bt2[tid]));
            sh[tid] = v;
        }
        __syncthreads();
        if (tid < REC) {
            const int c = tid;
            float acc = 0.f;
            if (c < 64) {
#pragma unroll 8
                for (int k = 0; k < IN_DIM; k++)
                    acc = fmaf(sh[k], __ldg(Wtau + k * ATTN_DIM + c), acc);
            } else {
                const int cc = c - 64;
#pragma unroll 8
                for (int k = 0; k < IN_DIM; k++)
                    acc = fmaf(sh[k], __ldg(Wh + k * OUT_DIM + cc), acc);
            }
            g_tau[t * REC + c] = acc;
        }
    }
}

// ------------------------------------------------------------------
// edge kernel: 16 lanes per edge, 2 edges per warp.
// red.add projected message directly into d_out.
// ------------------------------------------------------------------
__global__ void __launch_bounds__(256)
edge_kernel(const int* __restrict__ edges,
            const int* __restrict__ q_tau,
            const float* __restrict__ waW,
            const float* __restrict__ wab,
            float* __restrict__ out) {
    const int gw   = (blockIdx.x * blockDim.x + threadIdx.x) >> 5;
    const int lane = threadIdx.x & 31;
    const int e0   = gw << 1;
    if (e0 >= N_EDGE) return;          // whole warp exits together (N_EDGE even)

    const int h  = lane >> 4;
    const int sl = lane & 15;
    const int e  = e0 + h;

    const int* er = edges + (size_t)e * 7;
    const int r_idx = __ldg(er + 0);
    const int rel   = __ldg(er + 2);
    const int tauv  = __ldg(er + 4);
    const int sub   = __ldg(er + 5);
    const int obj   = __ldg(er + 6);

    const int tq = __ldg(q_tau + r_idx);
    const int t  = (tauv >= 0 ? tauv - tq : 0) + 365;   // 0..730

    const float4* np = reinterpret_cast<const float4*>(g_node + (size_t)sub * REC);
    const float4* rp = reinterpret_cast<const float4*>(g_rel  + rel   * REC);
    const float4* tp = reinterpret_cast<const float4*>(g_tau  + t     * REC);
    const float4* qp = reinterpret_cast<const float4*>(g_qpre + r_idx * ATTN_DIM);

    // attention: 64-wide, 4 per lane
    float4 a = np[sl], b = rp[sl], cq = qp[sl], d = tp[sl];
    float4 w = reinterpret_cast<const float4*>(waW)[sl];
    float p0 = fmaxf(a.x + b.x + cq.x + d.x, 0.f);
    float p1 = fmaxf(a.y + b.y + cq.y + d.y, 0.f);
    float p2 = fmaxf(a.z + b.z + cq.z + d.z, 0.f);
    float p3 = fmaxf(a.w + b.w + cq.w + d.w, 0.f);
    float s = fmaf(p0, w.x, fmaf(p1, w.y, fmaf(p2, w.z, p3 * w.w)));
#pragma unroll
    for (int off = 8; off > 0; off >>= 1)          // stays within the 16-lane half
        s += __shfl_xor_sync(0xFFFFFFFFu, s, off);
    const float alpha = 1.f / (1.f + __expf(-(s + __ldg(wab))));

    // projected message: 128-wide, 8 per lane (two float4 per table)
    const int mo = 16 + sl * 2;                    // float4 index: floats [64:192)
    float4 n0 = np[mo], n1 = np[mo + 1];
    float4 r0 = rp[mo], r1 = rp[mo + 1];
    float4 t0 = tp[mo], t1 = tp[mo + 1];

    float4 m0, m1;
    m0.x = alpha * (n0.x + r0.x + t0.x);  m0.y = alpha * (n0.y + r0.y + t0.y);
    m0.z = alpha * (n0.z + r0.z + t0.z);  m0.w = alpha * (n0.w + r0.w + t0.w);
    m1.x = alpha * (n1.x + r1.x + t1.x);  m1.y = alpha * (n1.y + r1.y + t1.y);
    m1.z = alpha * (n1.z + r1.z + t1.z);  m1.w = alpha * (n1.w + r1.w + t1.w);

    float* dst = out + (size_t)obj * OUT_DIM + sl * 8;
    asm volatile("red.global.add.v4.f32 [%0], {%1,%2,%3,%4};"
                 :: "l"(dst), "f"(m0.x), "f"(m0.y), "f"(m0.z), "f"(m0.w) : "memory");
    asm volatile("red.global.add.v4.f32 [%0], {%1,%2,%3,%4};"
                 :: "l"(dst + 4), "f"(m1.x), "f"(m1.y), "f"(m1.z), "f"(m1.w) : "memory");
}

// ------------------------------------------------------------------
// host launcher
// ------------------------------------------------------------------
extern "C" void kernel_launch(void* const* d_in, const int* in_sizes, int n_in,
                              void* d_out, int out_size) {
    // input order: q_sub, q_rel, q_tau, hidden, edges, [n_node],
    // old_nodes_new_idx, rela_embed, Ws, Wr, Wqr_W, Wqr_b, Wtau,
    // w_alpha_W, w_alpha_b, Wh, wt1, bt1, wt2, bt2
    int base = 5;
    if (n_in > 5 && in_sizes[5] == 1) base = 6;   // skip n_node scalar if present

    const int*   q_rel  = (const int*)  d_in[1];
    const int*   q_tau  = (const int*)  d_in[2];
    const float* hidden = (const float*)d_in[3];
    const int*   edges  = (const int*)  d_in[4];
    const float* rela   = (const float*)d_in[base + 1];
    const float* Ws     = (const float*)d_in[base + 2];
    const float* Wr     = (const float*)d_in[base + 3];
    const float* WqrW   = (const float*)d_in[base + 4];
    const float* Wqrb   = (const float*)d_in[base + 5];
    const float* Wtau   = (const float*)d_in[base + 6];
    const float* waW    = (const float*)d_in[base + 7];
    const float* wab    = (const float*)d_in[base + 8];
    const float* Wh     = (const float*)d_in[base + 9];
    const float* wt1    = (const float*)d_in[base + 10];
    const float* bt1    = (const float*)d_in[base + 11];
    const float* wt2    = (const float*)d_in[base + 12];
    const float* bt2    = (const float*)d_in[base + 13];
    float* out = (float*)d_out;

    cudaMemsetAsync(out, 0, (size_t)out_size * sizeof(float), 0);

    prep_kernel<<<NB_A + NB_B + NB_C + NB_D, 256>>>(
        hidden, rela, q_rel, Ws, Wr, WqrW, Wqrb, Wtau, Wh,
        wt1, bt1, wt2, bt2);

    // 2 edges per warp, 8 warps per block -> 16 edges/block
    edge_kernel<<<N_EDGE / 16, 256>>>(edges, q_tau, waW, wab, out);
}

// round 9
// speedup vs baseline: 1.1684x; 1.1046x over previous
#include <cuda_runtime.h>
#include <cuda_bf16.h>
#include <mma.h>
#include <math.h>
#include <stdint.h>

using namespace nvcuda;

#define N_NODE   50000
#define N_EDGE   500000
#define N_QUERY  64
#define IN_DIM   128
#define OUT_DIM  128
#define ATTN_DIM 64
#define N_RELTOT 401
#define N_TAU    731
#define REC      192      // 64 attn cols + 128 projected-message cols

// ---- scratch (device globals) ----
// g_node padded by 128 rows so the last MMA tile can store unguarded.
__device__ float g_node[(N_NODE + 128) * REC];   // [hidden@Ws | hidden@Wh]
__device__ float g_rel [N_RELTOT * REC];         // [rela@Wr   | rela@Wh]
__device__ float g_tau [N_TAU    * REC];         // [h_tau@Wtau| h_tau@Wh]
__device__ float g_qpre[N_QUERY  * ATTN_DIM];

// ================= prep kernel =================
// blocks [0, NB_A): node GEMM via wmma bf16x3, 128 rows/block
// [NB_A,+NB_B): rel table (16/blk); +NB_C: qpre (16/blk); +NB_D: tau (4 t/blk)
#define NB_A 391
#define NB_B 26
#define NB_C 4
#define NB_D 183

// dynamic smem byte offsets (part A); halves
#define LDA 144              // A row stride in halves (128 + 16 pad)
#define LDB 208              // B row stride in halves (192 + 16 pad)
#define SM_AH 0
#define SM_AL (SM_AH + 128 * LDA * 2)          // 36864
#define SM_BH (SM_AL + 128 * LDA * 2)          // 73728
#define SM_BL (SM_BH + 128 * LDB * 2)          // 126976
#define SM_TOT (SM_BL + 128 * LDB * 2)         // 180224

__global__ void __launch_bounds__(256)
prep_kernel(const float* __restrict__ hidden,
            const float* __restrict__ rela,
            const int*   __restrict__ q_rel,
            const float* __restrict__ Ws,
            const float* __restrict__ Wr,
            const float* __restrict__ WqrW,
            const float* __restrict__ Wqrb,
            const float* __restrict__ Wtau,
            const float* __restrict__ Wh,
            const float* __restrict__ wt1,
            const float* __restrict__ bt1,
            const float* __restrict__ wt2,
            const float* __restrict__ bt2) {
    extern __shared__ char smem[];
    const int tid = threadIdx.x;
    const int blk = blockIdx.x;

    if (blk < NB_A) {
        // ---------- node GEMM tile: rows [r0, r0+128), bf16x3 ----------
        const int r0 = blk * 128;
        __nv_bfloat16* Ah = reinterpret_cast<__nv_bfloat16*>(smem + SM_AH);
        __nv_bfloat16* Al = reinterpret_cast<__nv_bfloat16*>(smem + SM_AL);
        __nv_bfloat16* Bh = reinterpret_cast<__nv_bfloat16*>(smem + SM_BH);
        __nv_bfloat16* Bl = reinterpret_cast<__nv_bfloat16*>(smem + SM_BL);

        // stage A: 128 rows x 128 k (hi/lo split)
        for (int i = tid; i < 128 * 128; i += 256) {
            int row = i >> 7, k = i & 127;
            int r = r0 + row;
            float v = (r < N_NODE) ? hidden[(size_t)r * IN_DIM + k] : 0.f;
            __nv_bfloat16 hb = __float2bfloat16_rn(v);
            __nv_bfloat16 lb = __float2bfloat16_rn(v - __bfloat162float(hb));
            Ah[row * LDA + k] = hb;
            Al[row * LDA + k] = lb;
        }
        // stage B: B[k][n], n<64 -> Ws, else Wh
        for (int i = tid; i < 128 * 192; i += 256) {
            int k = i / 192, n = i - k * 192;
            float v = (n < 64) ? Ws[k * ATTN_DIM + n] : Wh[k * OUT_DIM + (n - 64)];
            __nv_bfloat16 hb = __float2bfloat16_rn(v);
            __nv_bfloat16 lb = __float2bfloat16_rn(v - __bfloat162float(hb));
            Bh[k * LDB + n] = hb;
            Bl[k * LDB + n] = lb;
        }
        __syncthreads();

        // warp w -> 16-row strip w, 12 col-tiles of 16
        const int wid = tid >> 5;
        wmma::fragment<wmma::accumulator, 16, 16, 16, float> acc[12];
#pragma unroll
        for (int ct = 0; ct < 12; ct++) wmma::fill_fragment(acc[ct], 0.f);

        wmma::fragment<wmma::matrix_a, 16, 16, 16, __nv_bfloat16, wmma::row_major> fah, fal;
        wmma::fragment<wmma::matrix_b, 16, 16, 16, __nv_bfloat16, wmma::row_major> fbh, fbl;

#pragma unroll
        for (int ks = 0; ks < 8; ks++) {
            wmma::load_matrix_sync(fah, Ah + wid * 16 * LDA + ks * 16, LDA);
            wmma::load_matrix_sync(fal, Al + wid * 16 * LDA + ks * 16, LDA);
#pragma unroll
            for (int ct = 0; ct < 12; ct++) {
                wmma::load_matrix_sync(fbh, Bh + ks * 16 * LDB + ct * 16, LDB);
                wmma::load_matrix_sync(fbl, Bl + ks * 16 * LDB + ct * 16, LDB);
                wmma::mma_sync(acc[ct], fah, fbh, acc[ct]);
                wmma::mma_sync(acc[ct], fah, fbl, acc[ct]);
                wmma::mma_sync(acc[ct], fal, fbh, acc[ct]);
            }
        }
        // store (g_node padded -> no row guard needed)
        float* dst = g_node + (size_t)(r0 + wid * 16) * REC;
#pragma unroll
        for (int ct = 0; ct < 12; ct++)
            wmma::store_matrix_sync(dst + ct * 16, acc[ct], REC, wmma::mem_row_major);
    } else if (blk < NB_A + NB_B) {
        // ---------- rel table ----------
        float* sh = reinterpret_cast<float*>(smem);
        const int rb = (blk - NB_A) * 16;
        for (int i = tid; i < 16 * IN_DIM; i += 256) {
            int rr = i >> 7, k = i & 127;
            int r = rb + rr;
            sh[rr * IN_DIM + k] = (r < N_RELTOT) ? rela[(size_t)r * IN_DIM + k] : 0.f;
        }
        __syncthreads();
        for (int o = tid; o < 16 * REC; o += 256) {
            int rr = o / REC, c = o - rr * REC;
            int r = rb + rr;
            if (r >= N_RELTOT) continue;
            const float* hrow = sh + rr * IN_DIM;
            float acc = 0.f;
            if (c < 64) {
#pragma unroll 8
                for (int k = 0; k < IN_DIM; k++)
                    acc = fmaf(hrow[k], __ldg(Wr + k * ATTN_DIM + c), acc);
            } else {
                const int cc = c - 64;
#pragma unroll 8
                for (int k = 0; k < IN_DIM; k++)
                    acc = fmaf(hrow[k], __ldg(Wh + k * OUT_DIM + cc), acc);
            }
            g_rel[r * REC + c] = acc;
        }
    } else if (blk < NB_A + NB_B + NB_C) {
        // ---------- qpre ----------
        float* sh = reinterpret_cast<float*>(smem);
        const int qb = (blk - NB_A - NB_B) * 16;
        for (int i = tid; i < 16 * IN_DIM; i += 256) {
            int qq = i >> 7, k = i & 127;
            int q = qb + qq;
            int rl = (q < N_QUERY) ? __ldg(q_rel + q) : 0;
            sh[qq * IN_DIM + k] = rela[(size_t)rl * IN_DIM + k];
        }
        __syncthreads();
        for (int o = tid; o < 16 * ATTN_DIM; o += 256) {
            int qq = o >> 6, c = o & 63;
            int q = qb + qq;
            if (q >= N_QUERY) continue;
            const float* hrow = sh + qq * IN_DIM;
            float acc = __ldg(Wqrb + c);
#pragma unroll 8
            for (int k = 0; k < IN_DIM; k++)
                acc = fmaf(hrow[k], __ldg(WqrW + k * ATTN_DIM + c), acc);
            g_qpre[q * ATTN_DIM + c] = acc;
        }
    } else {
        // ---------- tau table: 4 t per block ----------
        float* sh = reinterpret_cast<float*>(smem);
        const int tbase = (blk - NB_A - NB_B - NB_C) * 4;
        for (int tt = 0; tt < 4; tt++) {
            const int t = tbase + tt;
            if (t >= N_TAU) break;
            __syncthreads();
            const float dt = (float)(t - 365);
            if (tid < IN_DIM)
                sh[tid] = wt1[tid] * dt + bt1[tid] + sinf(fmaf(wt2[tid], dt, bt2[tid]));
            __syncthreads();
            if (tid < REC) {
                const int c = tid;
                float acc = 0.f;
                if (c < 64) {
#pragma unroll 8
                    for (int k = 0; k < IN_DIM; k++)
                        acc = fmaf(sh[k], __ldg(Wtau + k * ATTN_DIM + c), acc);
                } else {
                    const int cc = c - 64;
#pragma unroll 8
                    for (int k = 0; k < IN_DIM; k++)
                        acc = fmaf(sh[k], __ldg(Wh + k * OUT_DIM + cc), acc);
                }
                g_tau[t * REC + c] = acc;
            }
        }
    }
}

// ================= edge kernel =================
__global__ void __launch_bounds__(256)
edge_kernel(const int* __restrict__ edges,
            const int* __restrict__ q_tau,
            const float* __restrict__ waW,
            const float* __restrict__ wab,
            float* __restrict__ out) {
    const int gw   = (blockIdx.x * blockDim.x + threadIdx.x) >> 5;
    const int lane = threadIdx.x & 31;
    const int e0   = gw << 1;
    if (e0 >= N_EDGE) return;

    const int h  = lane >> 4;
    const int sl = lane & 15;
    const int e  = e0 + h;

    const int* er = edges + (size_t)e * 7;
    const int r_idx = __ldg(er + 0);
    const int rel   = __ldg(er + 2);
    const int tauv  = __ldg(er + 4);
    const int sub   = __ldg(er + 5);
    const int obj   = __ldg(er + 6);

    const int tq = __ldg(q_tau + r_idx);
    const int t  = (tauv >= 0 ? tauv - tq : 0) + 365;

    const float4* np = reinterpret_cast<const float4*>(g_node + (size_t)sub * REC);
    const float4* rp = reinterpret_cast<const float4*>(g_rel  + rel   * REC);
    const float4* tp = reinterpret_cast<const float4*>(g_tau  + t     * REC);
    const float4* qp = reinterpret_cast<const float4*>(g_qpre + r_idx * ATTN_DIM);

    float4 a = np[sl], b = rp[sl], cq = qp[sl], d = tp[sl];
    float4 w = reinterpret_cast<const float4*>(waW)[sl];
    float p0 = fmaxf(a.x + b.x + cq.x + d.x, 0.f);
    float p1 = fmaxf(a.y + b.y + cq.y + d.y, 0.f);
    float p2 = fmaxf(a.z + b.z + cq.z + d.z, 0.f);
    float p3 = fmaxf(a.w + b.w + cq.w + d.w, 0.f);
    float s = fmaf(p0, w.x, fmaf(p1, w.y, fmaf(p2, w.z, p3 * w.w)));
#pragma unroll
    for (int off = 8; off > 0; off >>= 1)
        s += __shfl_xor_sync(0xFFFFFFFFu, s, off);
    const float alpha = 1.f / (1.f + __expf(-(s + __ldg(wab))));

    const int mo = 16 + sl * 2;
    float4 n0 = np[mo], n1 = np[mo + 1];
    float4 r0 = rp[mo], r1 = rp[mo + 1];
    float4 t0 = tp[mo], t1 = tp[mo + 1];

    float4 m0, m1;
    m0.x = alpha * (n0.x + r0.x + t0.x);  m0.y = alpha * (n0.y + r0.y + t0.y);
    m0.z = alpha * (n0.z + r0.z + t0.z);  m0.w = alpha * (n0.w + r0.w + t0.w);
    m1.x = alpha * (n1.x + r1.x + t1.x);  m1.y = alpha * (n1.y + r1.y + t1.y);
    m1.z = alpha * (n1.z + r1.z + t1.z);  m1.w = alpha * (n1.w + r1.w + t1.w);

    float* dst = out + (size_t)obj * OUT_DIM + sl * 8;
    asm volatile("red.global.add.v4.f32 [%0], {%1,%2,%3,%4};"
                 :: "l"(dst), "f"(m0.x), "f"(m0.y), "f"(m0.z), "f"(m0.w) : "memory");
    asm volatile("red.global.add.v4.f32 [%0], {%1,%2,%3,%4};"
                 :: "l"(dst + 4), "f"(m1.x), "f"(m1.y), "f"(m1.z), "f"(m1.w) : "memory");
}

// ================= launcher =================
extern "C" void kernel_launch(void* const* d_in, const int* in_sizes, int n_in,
                              void* d_out, int out_size) {
    int base = 5;
    if (n_in > 5 && in_sizes[5] == 1) base = 6;

    const int*   q_rel  = (const int*)  d_in[1];
    const int*   q_tau  = (const int*)  d_in[2];
    const float* hidden = (const float*)d_in[3];
    const int*   edges  = (const int*)  d_in[4];
    const float* rela   = (const float*)d_in[base + 1];
    const float* Ws     = (const float*)d_in[base + 2];
    const float* Wr     = (const float*)d_in[base + 3];
    const float* WqrW   = (const float*)d_in[base + 4];
    const float* Wqrb   = (const float*)d_in[base + 5];
    const float* Wtau   = (const float*)d_in[base + 6];
    const float* waW    = (const float*)d_in[base + 7];
    const float* wab    = (const float*)d_in[base + 8];
    const float* Wh     = (const float*)d_in[base + 9];
    const float* wt1    = (const float*)d_in[base + 10];
    const float* bt1    = (const float*)d_in[base + 11];
    const float* wt2    = (const float*)d_in[base + 12];
    const float* bt2    = (const float*)d_in[base + 13];
    float* out = (float*)d_out;

    cudaFuncSetAttribute(prep_kernel,
                         cudaFuncAttributeMaxDynamicSharedMemorySize, SM_TOT);

    cudaMemsetAsync(out, 0, (size_t)out_size * sizeof(float), 0);

    prep_kernel<<<NB_A + NB_B + NB_C + NB_D, 256, SM_TOT>>>(
        hidden, rela, q_rel, Ws, Wr, WqrW, Wqrb, Wtau, Wh,
        wt1, bt1, wt2, bt2);

    edge_kernel<<<N_EDGE / 16, 256>>>(edges, q_tau, waW, wab, out);
}

// round 11
// speedup vs baseline: 1.3628x; 1.1664x over previous
#include <cuda_runtime.h>
#include <cuda_bf16.h>
#include <mma.h>
#include <math.h>
#include <stdint.h>

using namespace nvcuda;
typedef unsigned long long ull;

#define N_NODE   50000
#define N_EDGE   500000
#define N_QUERY  64
#define IN_DIM   128
#define OUT_DIM  128
#define ATTN_DIM 64
#define N_RELTOT 401
#define N_TAU    731
#define REC      192        // 64 attn cols + 128 projected-message cols
#define NROWPAD  50048      // 391 * 128

// ---- scratch (device globals) ----
__device__ float g_node[NROWPAD * REC];          // [hidden@Ws | hidden@Wh]
__device__ float g_rel [N_RELTOT * REC];         // [rela@Wr   | rela@Wh]
__device__ float g_tau [N_TAU    * REC];         // [h_tau@Wtau| h_tau@Wh]
__device__ float g_qpre[N_QUERY  * ATTN_DIM];
__device__ __nv_bfloat16 gAh[NROWPAD * IN_DIM];  // hidden hi
__device__ __nv_bfloat16 gAl[NROWPAD * IN_DIM];  // hidden lo
__device__ __nv_bfloat16 gBh[IN_DIM * REC];      // [Ws|Wh] hi, row-major [k][n]
__device__ __nv_bfloat16 gBl[IN_DIM * REC];      // [Ws|Wh] lo

__device__ __forceinline__ void cvt_hilo(float v, unsigned short& h, unsigned short& l) {
    __nv_bfloat16 hb = __float2bfloat16_rn(v);
    __nv_bfloat16 lb = __float2bfloat16_rn(v - __bfloat162float(hb));
    h = __bfloat16_as_ushort(hb);
    l = __bfloat16_as_ushort(lb);
}

// ================= kernel 0: convert + small tables =================
// blocks [0,400): convert hidden -> gAh/gAl (float4 grid-stride)
// block  400    : convert [Ws|Wh] -> gBh/gBl
// [401,427): rel table; [427,431): qpre; [431,614): tau (4 t/blk)
#define K0_CV   400
#define K0_B    (K0_CV)          // single block id == 400
#define K0_REL  (K0_CV + 1)      // 401
#define K0_QP   (K0_REL + 26)    // 427
#define K0_TAU  (K0_QP + 4)      // 431
#define K0_END  (K0_TAU + 183)   // 614

__global__ void __launch_bounds__(256)
prep_aux_kernel(const float* __restrict__ hidden,
                const float* __restrict__ rela,
                const int*   __restrict__ q_rel,
                const float* __restrict__ Ws,
                const float* __restrict__ Wr,
                const float* __restrict__ WqrW,
                const float* __restrict__ Wqrb,
                const float* __restrict__ Wtau,
                const float* __restrict__ Wh,
                const float* __restrict__ wt1,
                const float* __restrict__ bt1,
                const float* __restrict__ wt2,
                const float* __restrict__ bt2) {
    __shared__ float sh[16 * IN_DIM];
    const int tid = threadIdx.x;
    const int blk = blockIdx.x;

    if (blk < K0_CV) {
        // ---- convert hidden (pad rows -> 0) ----
        const int total = NROWPAD * (IN_DIM / 4);     // float4 count
        const int stride = K0_CV * 256;
        const float4* src = reinterpret_cast<const float4*>(hidden);
        ull* dh = reinterpret_cast<ull*>(gAh);
        ull* dl = reinterpret_cast<ull*>(gAl);
        const int limit = N_NODE * (IN_DIM / 4);
        for (int i = blk * 256 + tid; i < total; i += stride) {
            float4 v = (i < limit) ? src[i] : make_float4(0.f, 0.f, 0.f, 0.f);
            unsigned short h0, l0, h1, l1, h2, l2, h3, l3;
            cvt_hilo(v.x, h0, l0); cvt_hilo(v.y, h1, l1);
            cvt_hilo(v.z, h2, l2); cvt_hilo(v.w, h3, l3);
            dh[i] = (ull)h0 | ((ull)h1 << 16) | ((ull)h2 << 32) | ((ull)h3 << 48);
            dl[i] = (ull)l0 | ((ull)l1 << 16) | ((ull)l2 << 32) | ((ull)l3 << 48);
        }
    } else if (blk == K0_B) {
        // ---- convert B = [Ws|Wh] ----
        for (int i = tid; i < IN_DIM * REC; i += 256) {
            int k = i / REC, n = i - k * REC;
            float v = (n < 64) ? Ws[k * ATTN_DIM + n] : Wh[k * OUT_DIM + (n - 64)];
            unsigned short h, l;
            cvt_hilo(v, h, l);
            gBh[i] = __ushort_as_bfloat16(h);
            gBl[i] = __ushort_as_bfloat16(l);
        }
    } else if (blk < K0_QP) {
        // ---- rel table ----
        const int rb = (blk - K0_REL) * 16;
        for (int i = tid; i < 16 * IN_DIM; i += 256) {
            int rr = i >> 7, k = i & 127;
            int r = rb + rr;
            sh[rr * IN_DIM + k] = (r < N_RELTOT) ? rela[(size_t)r * IN_DIM + k] : 0.f;
        }
        __syncthreads();
        for (int o = tid; o < 16 * REC; o += 256) {
            int rr = o / REC, c = o - rr * REC;
            int r = rb + rr;
            if (r >= N_RELTOT) continue;
            const float* hrow = sh + rr * IN_DIM;
            float acc = 0.f;
            if (c < 64) {
#pragma unroll 8
                for (int k = 0; k < IN_DIM; k++)
                    acc = fmaf(hrow[k], __ldg(Wr + k * ATTN_DIM + c), acc);
            } else {
                const int cc = c - 64;
#pragma unroll 8
                for (int k = 0; k < IN_DIM; k++)
                    acc = fmaf(hrow[k], __ldg(Wh + k * OUT_DIM + cc), acc);
            }
            g_rel[r * REC + c] = acc;
        }
    } else if (blk < K0_TAU) {
        // ---- qpre ----
        const int qb = (blk - K0_QP) * 16;
        for (int i = tid; i < 16 * IN_DIM; i += 256) {
            int qq = i >> 7, k = i & 127;
            int q = qb + qq;
            int rl = (q < N_QUERY) ? __ldg(q_rel + q) : 0;
            sh[qq * IN_DIM + k] = rela[(size_t)rl * IN_DIM + k];
        }
        __syncthreads();
        for (int o = tid; o < 16 * ATTN_DIM; o += 256) {
            int qq = o >> 6, c = o & 63;
            int q = qb + qq;
            if (q >= N_QUERY) continue;
            const float* hrow = sh + qq * IN_DIM;
            float acc = __ldg(Wqrb + c);
#pragma unroll 8
            for (int k = 0; k < IN_DIM; k++)
                acc = fmaf(hrow[k], __ldg(WqrW + k * ATTN_DIM + c), acc);
            g_qpre[q * ATTN_DIM + c] = acc;
        }
    } else {
        // ---- tau table: 4 t per block ----
        const int tbase = (blk - K0_TAU) * 4;
        for (int tt = 0; tt < 4; tt++) {
            const int t = tbase + tt;
            if (t >= N_TAU) break;
            __syncthreads();
            const float dt = (float)(t - 365);
            if (tid < IN_DIM)
                sh[tid] = wt1[tid] * dt + bt1[tid] + sinf(fmaf(wt2[tid], dt, bt2[tid]));
            __syncthreads();
            if (tid < REC) {
                const int c = tid;
                float acc = 0.f;
                if (c < 64) {
#pragma unroll 8
                    for (int k = 0; k < IN_DIM; k++)
                        acc = fmaf(sh[k], __ldg(Wtau + k * ATTN_DIM + c), acc);
                } else {
                    const int cc = c - 64;
#pragma unroll 8
                    for (int k = 0; k < IN_DIM; k++)
                        acc = fmaf(sh[k], __ldg(Wh + k * OUT_DIM + cc), acc);
                }
                g_tau[t * REC + c] = acc;
            }
        }
    }
}

// ================= kernel 1: persistent node GEMM =================
// 131 blocks x 3 tiles (128 rows each). B staged once per block.
#define N_TILE   391
#define GB       131                // blocks
#define TPB      3                  // tiles per block
#define LDA 136                     // A smem row stride (halves): 272B, 16B mod 128 shift
#define LDB 200                     // B smem row stride (halves): 400B, 16B mod 128 shift
#define SA_H 0
#define SA_L (SA_H + 128 * LDA * 2)        // 34816
#define SB_H (SA_L + 128 * LDA * 2)        // 69632
#define SB_L (SB_H + 128 * LDB * 2)        // 120832
#define SM1_TOT (SB_L + 128 * LDB * 2)     // 172032

__global__ void __launch_bounds__(256)
node_gemm_kernel() {
    extern __shared__ char smem[];
    __nv_bfloat16* Ah = reinterpret_cast<__nv_bfloat16*>(smem + SA_H);
    __nv_bfloat16* Al = reinterpret_cast<__nv_bfloat16*>(smem + SA_L);
    __nv_bfloat16* Bh = reinterpret_cast<__nv_bfloat16*>(smem + SB_H);
    __nv_bfloat16* Bl = reinterpret_cast<__nv_bfloat16*>(smem + SB_L);
    const int tid = threadIdx.x;
    const int wid = tid >> 5;

    // stage B once: 128 rows x 24 float4 per row (192 halves)
    {
        const float4* sh4 = reinterpret_cast<const float4*>(gBh);
        const float4* sl4 = reinterpret_cast<const float4*>(gBl);
        for (int i = tid; i < 128 * 24; i += 256) {
            int k = i / 24, c = i - k * 24;
            *reinterpret_cast<float4*>(Bh + k * LDB + c * 8) = sh4[k * 24 + c];
            *reinterpret_cast<float4*>(Bl + k * LDB + c * 8) = sl4[k * 24 + c];
        }
    }

    wmma::fragment<wmma::matrix_a, 16, 16, 16, __nv_bfloat16, wmma::row_major> fah, fal;
    wmma::fragment<wmma::matrix_b, 16, 16, 16, __nv_bfloat16, wmma::row_major> fbh, fbl;

    for (int s = 0; s < TPB; s++) {
        const int tile = blockIdx.x * TPB + s;
        if (tile >= N_TILE) break;
        const int r0 = tile * 128;

        // stage A tile: 128 rows x 16 float4 (128 halves) per row
        __syncthreads();
        {
            const float4* ah4 = reinterpret_cast<const float4*>(gAh);
            const float4* al4 = reinterpret_cast<const float4*>(gAl);
            for (int i = tid; i < 128 * 16; i += 256) {
                int row = i >> 4, c = i & 15;
                *reinterpret_cast<float4*>(Ah + row * LDA + c * 8) = ah4[(size_t)(r0 + row) * 16 + c];
                *reinterpret_cast<float4*>(Al + row * LDA + c * 8) = al4[(size_t)(r0 + row) * 16 + c];
            }
        }
        __syncthreads();

        wmma::fragment<wmma::accumulator, 16, 16, 16, float> acc[12];
#pragma unroll
        for (int ct = 0; ct < 12; ct++) wmma::fill_fragment(acc[ct], 0.f);

#pragma unroll
        for (int ks = 0; ks < 8; ks++) {
            wmma::load_matrix_sync(fah, Ah + wid * 16 * LDA + ks * 16, LDA);
            wmma::load_matrix_sync(fal, Al + wid * 16 * LDA + ks * 16, LDA);
#pragma unroll
            for (int ct = 0; ct < 12; ct++) {
                wmma::load_matrix_sync(fbh, Bh + ks * 16 * LDB + ct * 16, LDB);
                wmma::load_matrix_sync(fbl, Bl + ks * 16 * LDB + ct * 16, LDB);
                wmma::mma_sync(acc[ct], fah, fbh, acc[ct]);
                wmma::mma_sync(acc[ct], fah, fbl, acc[ct]);
                wmma::mma_sync(acc[ct], fal, fbh, acc[ct]);
            }
        }
        float* dst = g_node + (size_t)(r0 + wid * 16) * REC;
#pragma unroll
        for (int ct = 0; ct < 12; ct++)
            wmma::store_matrix_sync(dst + ct * 16, acc[ct], REC, wmma::mem_row_major);
    }
}

// ================= edge kernel (unchanged) =================
__global__ void __launch_bounds__(256)
edge_kernel(const int* __restrict__ edges,
            const int* __restrict__ q_tau,
            const float* __restrict__ waW,
            const float* __restrict__ wab,
            float* __restrict__ out) {
    const int gw   = (blockIdx.x * blockDim.x + threadIdx.x) >> 5;
    const int lane = threadIdx.x & 31;
    const int e0   = gw << 1;
    if (e0 >= N_EDGE) return;

    const int h  = lane >> 4;
    const int sl = lane & 15;
    const int e  = e0 + h;

    const int* er = edges + (size_t)e * 7;
    const int r_idx = __ldg(er + 0);
    const int rel   = __ldg(er + 2);
    const int tauv  = __ldg(er + 4);
    const int sub   = __ldg(er + 5);
    const int obj   = __ldg(er + 6);

    const int tq = __ldg(q_tau + r_idx);
    const int t  = (tauv >= 0 ? tauv - tq : 0) + 365;

    const float4* np = reinterpret_cast<const float4*>(g_node + (size_t)sub * REC);
    const float4* rp = reinterpret_cast<const float4*>(g_rel  + rel   * REC);
    const float4* tp = reinterpret_cast<const float4*>(g_tau  + t     * REC);
    const float4* qp = reinterpret_cast<const float4*>(g_qpre + r_idx * ATTN_DIM);

    float4 a = np[sl], b = rp[sl], cq = qp[sl], d = tp[sl];
    float4 w = reinterpret_cast<const float4*>(waW)[sl];
    float p0 = fmaxf(a.x + b.x + cq.x + d.x, 0.f);
    float p1 = fmaxf(a.y + b.y + cq.y + d.y, 0.f);
    float p2 = fmaxf(a.z + b.z + cq.z + d.z, 0.f);
    float p3 = fmaxf(a.w + b.w + cq.w + d.w, 0.f);
    float s = fmaf(p0, w.x, fmaf(p1, w.y, fmaf(p2, w.z, p3 * w.w)));
#pragma unroll
    for (int off = 8; off > 0; off >>= 1)
        s += __shfl_xor_sync(0xFFFFFFFFu, s, off);
    const float alpha = 1.f / (1.f + __expf(-(s + __ldg(wab))));

    const int mo = 16 + sl * 2;
    float4 n0 = np[mo], n1 = np[mo + 1];
    float4 r0 = rp[mo], r1 = rp[mo + 1];
    float4 t0 = tp[mo], t1 = tp[mo + 1];

    float4 m0, m1;
    m0.x = alpha * (n0.x + r0.x + t0.x);  m0.y = alpha * (n0.y + r0.y + t0.y);
    m0.z = alpha * (n0.z + r0.z + t0.z);  m0.w = alpha * (n0.w + r0.w + t0.w);
    m1.x = alpha * (n1.x + r1.x + t1.x);  m1.y = alpha * (n1.y + r1.y + t1.y);
    m1.z = alpha * (n1.z + r1.z + t1.z);  m1.w = alpha * (n1.w + r1.w + t1.w);

    float* dst = out + (size_t)obj * OUT_DIM + sl * 8;
    asm volatile("red.global.add.v4.f32 [%0], {%1,%2,%3,%4};"
                 :: "l"(dst), "f"(m0.x), "f"(m0.y), "f"(m0.z), "f"(m0.w) : "memory");
    asm volatile("red.global.add.v4.f32 [%0], {%1,%2,%3,%4};"
                 :: "l"(dst + 4), "f"(m1.x), "f"(m1.y), "f"(m1.z), "f"(m1.w) : "memory");
}

// ================= launcher =================
extern "C" void kernel_launch(void* const* d_in, const int* in_sizes, int n_in,
                              void* d_out, int out_size) {
    int base = 5;
    if (n_in > 5 && in_sizes[5] == 1) base = 6;

    const int*   q_rel  = (const int*)  d_in[1];
    const int*   q_tau  = (const int*)  d_in[2];
    const float* hidden = (const float*)d_in[3];
    const int*   edges  = (const int*)  d_in[4];
    const float* rela   = (const float*)d_in[base + 1];
    const float* Ws     = (const float*)d_in[base + 2];
    const float* Wr     = (const float*)d_in[base + 3];
    const float* WqrW   = (const float*)d_in[base + 4];
    const float* Wqrb   = (const float*)d_in[base + 5];
    const float* Wtau   = (const float*)d_in[base + 6];
    const float* waW    = (const float*)d_in[base + 7];
    const float* wab    = (const float*)d_in[base + 8];
    const float* Wh     = (const float*)d_in[base + 9];
    const float* wt1    = (const float*)d_in[base + 10];
    const float* bt1    = (const float*)d_in[base + 11];
    const float* wt2    = (const float*)d_in[base + 12];
    const float* bt2    = (const float*)d_in[base + 13];
    float* out = (float*)d_out;

    cudaFuncSetAttribute(node_gemm_kernel,
                         cudaFuncAttributeMaxDynamicSharedMemorySize, SM1_TOT);

    cudaMemsetAsync(out, 0, (size_t)out_size * sizeof(float), 0);

    prep_aux_kernel<<<K0_END, 256>>>(
        hidden, rela, q_rel, Ws, Wr, WqrW, Wqrb, Wtau, Wh,
        wt1, bt1, wt2, bt2);

    node_gemm_kernel<<<GB, 256, SM1_TOT>>>();

    edge_kernel<<<N_EDGE / 16, 256>>>(edges, q_tau, waW, wab, out);
}